// round 1
// baseline (speedup 1.0000x reference)
#include <cuda_runtime.h>
#include <cuda_bf16.h>

// Problem: DotProductAttention_83476984365340
// Reference: softmax over a SINGLETON axis => weights are identically 1.0.
// Output context[b, d] = sum over t of values[b, t, d].
// So the kernel is a pure column-sum of `values` [B=32, T=4096, D=1024].
// Only `values` (d_in[2]) is needed: 512 MiB HBM read -> HBM-bound, ~85us floor.

#define B_DIM 32
#define T_DIM 4096
#define D_DIM 1024
#define T_CHUNKS 16
#define T_PER_CHUNK (T_DIM / T_CHUNKS)   // 256
#define THREADS 256                      // 256 threads * float4 = 1024 = D

__global__ __launch_bounds__(THREADS, 8)
void values_colsum_kernel(const float* __restrict__ values, float* __restrict__ out)
{
    const int b     = blockIdx.y;            // 0..31
    const int chunk = blockIdx.x;            // 0..15
    const int tid   = threadIdx.x;           // 0..255

    // Each thread owns 4 consecutive d's via float4.
    const int d4 = tid;                       // float4 index within row (0..255)

    const float4* __restrict__ vbase =
        reinterpret_cast<const float4*>(values) +
        (size_t)b * T_DIM * (D_DIM / 4) +
        (size_t)chunk * T_PER_CHUNK * (D_DIM / 4) +
        d4;

    float4 acc = make_float4(0.f, 0.f, 0.f, 0.f);

    // 256 rows of t, fully coalesced 128B/warp per iteration.
    #pragma unroll 8
    for (int t = 0; t < T_PER_CHUNK; ++t) {
        float4 v = vbase[(size_t)t * (D_DIM / 4)];
        acc.x += v.x;
        acc.y += v.y;
        acc.z += v.z;
        acc.w += v.w;
    }

    float* o = out + (size_t)b * D_DIM + d4 * 4;
    atomicAdd(o + 0, acc.x);
    atomicAdd(o + 1, acc.y);
    atomicAdd(o + 2, acc.z);
    atomicAdd(o + 3, acc.w);
}

extern "C" void kernel_launch(void* const* d_in, const int* in_sizes, int n_in,
                              void* d_out, int out_size)
{
    // Input order per reference setup_inputs(): query, keys, values, W
    const float* values = (const float*)d_in[2];
    float* out = (float*)d_out;

    // d_out is poisoned; zero it (memset node is graph-capturable).
    cudaMemsetAsync(out, 0, (size_t)out_size * sizeof(float));

    dim3 grid(T_CHUNKS, B_DIM);
    values_colsum_kernel<<<grid, THREADS>>>(values, out);
}

// round 2
// speedup vs baseline: 1.0108x; 1.0108x over previous
#include <cuda_runtime.h>
#include <cuda_bf16.h>

// Problem: DotProductAttention_83476984365340
// softmax over singleton axis == 1.0 -> output = values.sum(axis=1).
// Pure HBM-bound column sum of values [32, 4096, 1024] f32 (512 MiB read).
//
// R1: 82.9% DRAM @ 512 CTAs, occ 40.7% -> latency/MLP-limited, not at ceiling.
// R2 change: 1024 CTAs + front-batched 8x LDG.128 per loop iter (MLP_p1=8)
//            + streaming loads (__ldcs) + dual accumulator chains.

#define B_DIM 32
#define T_DIM 4096
#define D_DIM 1024
#define T_CHUNKS 32
#define T_PER_CHUNK (T_DIM / T_CHUNKS)   // 128
#define THREADS 256                       // 256 threads * float4 = 1024 = D
#define BATCH 8                           // loads in flight per loop iteration

__global__ __launch_bounds__(THREADS, 8)
void values_colsum_kernel(const float* __restrict__ values, float* __restrict__ out)
{
    const int b     = blockIdx.y;            // 0..31
    const int chunk = blockIdx.x;            // 0..T_CHUNKS-1
    const int d4    = threadIdx.x;           // float4 index within row (0..255)

    const float4* __restrict__ p =
        reinterpret_cast<const float4*>(values) +
        (size_t)b * T_DIM * (D_DIM / 4) +
        (size_t)chunk * T_PER_CHUNK * (D_DIM / 4) +
        d4;

    float4 acc0 = make_float4(0.f, 0.f, 0.f, 0.f);
    float4 acc1 = make_float4(0.f, 0.f, 0.f, 0.f);

    #pragma unroll 4
    for (int it = 0; it < T_PER_CHUNK / BATCH; ++it) {
        // Front-batch BATCH independent 128-bit streaming loads -> MLP_p1 = 8.
        float4 v[BATCH];
        #pragma unroll
        for (int k = 0; k < BATCH; ++k)
            v[k] = __ldcs(p + (size_t)k * (D_DIM / 4));
        p += (size_t)BATCH * (D_DIM / 4);

        // Two independent accumulator chains.
        #pragma unroll
        for (int k = 0; k < BATCH; k += 2) {
            acc0.x += v[k].x;   acc0.y += v[k].y;
            acc0.z += v[k].z;   acc0.w += v[k].w;
            acc1.x += v[k+1].x; acc1.y += v[k+1].y;
            acc1.z += v[k+1].z; acc1.w += v[k+1].w;
        }
    }

    acc0.x += acc1.x; acc0.y += acc1.y; acc0.z += acc1.z; acc0.w += acc1.w;

    float* o = out + (size_t)b * D_DIM + d4 * 4;
    atomicAdd(o + 0, acc0.x);
    atomicAdd(o + 1, acc0.y);
    atomicAdd(o + 2, acc0.z);
    atomicAdd(o + 3, acc0.w);
}

extern "C" void kernel_launch(void* const* d_in, const int* in_sizes, int n_in,
                              void* d_out, int out_size)
{
    // Input order per reference setup_inputs(): query, keys, values, W
    const float* values = (const float*)d_in[2];
    float* out = (float*)d_out;

    cudaMemsetAsync(out, 0, (size_t)out_size * sizeof(float));

    dim3 grid(T_CHUNKS, B_DIM);
    values_colsum_kernel<<<grid, THREADS>>>(values, out);
}